// round 14
// baseline (speedup 1.0000x reference)
#include <cuda_runtime.h>
#include <cstdint>

// ============================================================================
// QuantumNeuralLayer: out = x @ W.T + (b + 0.1*q); q batch-independent.
// 262144x256x64 fp32 GEMM via mma.sync tf32 — R6 config verbatim (measured
// best: 66.0us kernel, 4.84 TB/s; six structural BW experiments all pinned
// at 4.3-4.8 TB/s => chip-level ceiling for this traffic mix).
// R14 = R6 with grid=128: 1024 tiles / 128 CTAs = exactly 8 each, erasing
// the 3.9% static-assignment tail while preserving per-CTA DRAM locality
// (R13 showed dynamic stealing destroys locality and loses more than the
// tail gains). If the ceiling is chip-level, fewer CTAs sustain the same
// aggregate BW and the kernel shortens by the tail fraction.
// ============================================================================

#define INV_SQRT2 0.70710678118654752440f

static constexpr int B_TOTAL = 262144;
static constexpr int KDIM    = 256;
static constexpr int ODIM    = 64;
static constexpr int TILE_M  = 256;                 // 8 warps x 32 rows
static constexpr int NTILES  = B_TOTAL / TILE_M;    // 1024
static constexpr int NTHREADS = 256;
static constexpr int NCTAS   = 128;                 // 1024 % 128 == 0: no tail

static constexpr int KCHUNK   = 32;                 // floats per stage
static constexpr int SPT      = KDIM / KCHUNK;      // 8 stages per tile
static constexpr int APITCH   = 36;                 // floats; frag-conflict-free
static constexpr int ASTAGE_F = TILE_M * APITCH;    // 9216 floats = 36 KB
static constexpr int WF_F     = 4 * ASTAGE_F;       // 36864
static constexpr int BIAS_F   = WF_F + 16384;       // 53248
static constexpr int HA_F     = BIAS_F + 64;
static constexpr int HC_F     = HA_F + 64;
static constexpr int SMEM_F   = HC_F + 64;
static constexpr int SMEM_BYTES = SMEM_F * 4;       // 213760 B

// ---------------------------------------------------------------------------
__device__ __forceinline__ uint32_t smem_u32(const void* p) {
    uint32_t a;
    asm("{ .reg .u64 t; cvta.to.shared.u64 t, %1; cvt.u32.u64 %0, t; }" : "=r"(a) : "l"(p));
    return a;
}
__device__ __forceinline__ void cp_async16(uint32_t s, const void* g) {
    asm volatile("cp.async.cg.shared.global [%0], [%1], 16;" :: "r"(s), "l"(g));
}
#define CP_COMMIT() asm volatile("cp.async.commit_group;" ::: "memory")
#define CP_WAIT_2() asm volatile("cp.async.wait_group 2;" ::: "memory")

__device__ __forceinline__ uint32_t f2tf32(float f) {
    uint32_t u;
    asm("cvt.rna.tf32.f32 %0, %1;" : "=r"(u) : "f"(f));
    return u;
}

__device__ __forceinline__ void mma_tf32(float c[4], uint32_t a0, uint32_t a1,
                                         uint32_t a2, uint32_t a3,
                                         uint32_t b0, uint32_t b1) {
    asm volatile(
        "mma.sync.aligned.m16n8k8.row.col.f32.tf32.tf32.f32 "
        "{%0,%1,%2,%3}, {%4,%5,%6,%7}, {%8,%9}, {%0,%1,%2,%3};"
        : "+f"(c[0]), "+f"(c[1]), "+f"(c[2]), "+f"(c[3])
        : "r"(a0), "r"(a1), "r"(a2), "r"(a3), "r"(b0), "r"(b1));
}

// ---------------------------------------------------------------------------
__global__ void __launch_bounds__(NTHREADS, 1)
qnl_kernel(const float* __restrict__ x, const float* __restrict__ W,
           const float* __restrict__ bvec, const float* __restrict__ phase,
           const float* __restrict__ ent, float* __restrict__ out) {
    extern __shared__ float smemf[];
    const uint32_t sb = smem_u32(smemf);
    const int tid  = threadIdx.x;
    const int wid  = tid >> 5;
    const int lane = tid & 31;
    const int bid  = blockIdx.x;

    // Warp owns rows [wid*32, wid*32+32); m-frags at +0 and +16.
    const int wrow = wid * 32;
    const int arow = wrow + (lane >> 2);

    const int H = SPT * (NTILES / NCTAS);   // 64 stages, identical for all CTAs

    // Per-warp stage load: this warp's 32 rows of k-chunk (jq&7) of tile
    // (jq>>3), into ring slot jq&3. 256 x 16B chunks -> 8 per lane.
    auto load_stage = [&](int jq) {
        const int tile = bid + (jq >> 3) * NCTAS;
        const float* src = x + (size_t)tile * TILE_M * KDIM + (jq & 7) * KCHUNK;
        const uint32_t abase = sb + (uint32_t)((jq & 3) * ASTAGE_F + wrow * APITCH) * 4;
#pragma unroll
        for (int i = 0; i < 8; i++) {
            int c  = lane + 32 * i;        // 0..255
            int r  = c >> 3;               // local row 0..31
            int kc = c & 7;                // 16B chunk within 32-float chunk
            cp_async16(abase + (uint32_t)(r * APITCH + kc * 4) * 4,
                       src + (size_t)(wrow + r) * KDIM + kc * 4);
        }
        CP_COMMIT();
    };

    // Prologue: fill 3 stages (per warp), prep Wf + bias under the latency.
    load_stage(0);
    load_stage(1);
    load_stage(2);

    // --- W fragments: tf32-rounded, layout [s(32)][nt(8)][lane(32)] float2 ---
    for (int e = tid; e < 8192; e += NTHREADS) {
        int le = e & 31;
        int nt = (e >> 5) & 7;
        int s  = e >> 8;
        int n = nt * 8 + (le >> 2);
        int k = s * 8 + (le & 3);
        float2 wf;
        wf.x = __uint_as_float(f2tf32(W[n * KDIM + k]));
        wf.y = __uint_as_float(f2tf32(W[n * KDIM + k + 4]));
        *(float2*)(smemf + WF_F + 2 * e) = wf;
    }

    // --- bias_eff = b + 0.1*quantum (batch-independent) ---
    {
        float a = 1.0f, c = 0.0f;
        for (int d = 0; d < 3; d++) {
            if (tid < 64) {
                float ph = phase[d * 64 + tid];
                smemf[HA_F + tid] = (a + c) * INV_SQRT2 * sinf(ph);
                smemf[HC_F + tid] = (a - c) * INV_SQRT2 * cosf(ph);
            }
            __syncthreads();
            if (tid < 64) {
                float sa = 0.0f, sc = 0.0f;
#pragma unroll
                for (int i = 0; i < 64; i++) {
                    float e = ent[i * 64 + tid];
                    sa += smemf[HA_F + i] * e;
                    sc += smemf[HC_F + i] * e;
                }
                a = sa; c = sc;
            }
            __syncthreads();
        }
        if (tid < 64) smemf[BIAS_F + tid] = bvec[tid] + 0.1f * (a * a + c * c);
    }
    __syncthreads();   // Wf + bias visible; ONLY CTA-wide barrier in kernel

    float2 bias[8];
#pragma unroll
    for (int nt = 0; nt < 8; nt++) {
        int col = nt * 8 + 2 * (lane & 3);
        bias[nt].x = smemf[BIAS_F + col];
        bias[nt].y = smemf[BIAS_F + col + 1];
    }

    float acc[2][8][4];
#pragma unroll
    for (int mb = 0; mb < 2; mb++)
#pragma unroll
        for (int nt = 0; nt < 8; nt++)
#pragma unroll
            for (int q = 0; q < 4; q++) acc[mb][nt][q] = 0.0f;

    const float2* Wb = (const float2*)(smemf + WF_F);

    for (int j = 0; j < H; j++) {
        CP_WAIT_2();       // this lane's stage-j chunks resident
        __syncwarp();      // whole warp's chunks resident

        if (j + 3 < H) load_stage(j + 3);
        else CP_COMMIT();  // keep group accounting uniform

        const float* Ab = smemf + (j & 3) * ASTAGE_F + arow * APITCH + (lane & 3);
        const int sbase = (j & 7) * 4;

#pragma unroll
        for (int sl = 0; sl < 4; sl++) {
            const int ko = sl * 8;
            uint32_t a0 = f2tf32(Ab[ko]);
            uint32_t a1 = f2tf32(Ab[ko + 8 * APITCH]);
            uint32_t a2 = f2tf32(Ab[ko + 4]);
            uint32_t a3 = f2tf32(Ab[ko + 4 + 8 * APITCH]);
            uint32_t b0 = f2tf32(Ab[ko + 16 * APITCH]);
            uint32_t b1 = f2tf32(Ab[ko + 24 * APITCH]);
            uint32_t b2 = f2tf32(Ab[ko + 4 + 16 * APITCH]);
            uint32_t b3 = f2tf32(Ab[ko + 4 + 24 * APITCH]);
            const int s = sbase + sl;
#pragma unroll
            for (int nt = 0; nt < 8; nt++) {
                float2 wf = Wb[(s * 8 + nt) * 32 + lane];
                uint32_t w0 = __float_as_uint(wf.x);
                uint32_t w1 = __float_as_uint(wf.y);
                mma_tf32(acc[0][nt], a0, a1, a2, a3, w0, w1);
                mma_tf32(acc[1][nt], b0, b1, b2, b3, w0, w1);
            }
        }

        if ((j & 7) == 7) {
            // Tile complete: per-warp epilogue, no barriers.
            const int tile = bid + (j >> 3) * NCTAS;
            const int row0 = tile * TILE_M + arow;
            float* o0 = out + (size_t)row0 * ODIM + 2 * (lane & 3);
#pragma unroll
            for (int mb = 0; mb < 2; mb++) {
                float* om = o0 + (size_t)(mb * 16) * ODIM;
#pragma unroll
                for (int nt = 0; nt < 8; nt++) {
                    const int cb = nt * 8;
                    float2 v0 = {acc[mb][nt][0] + bias[nt].x,
                                 acc[mb][nt][1] + bias[nt].y};
                    float2 v1 = {acc[mb][nt][2] + bias[nt].x,
                                 acc[mb][nt][3] + bias[nt].y};
                    *(float2*)(om + cb)            = v0;
                    *(float2*)(om + cb + 8 * ODIM) = v1;
                    acc[mb][nt][0] = acc[mb][nt][1] = 0.0f;
                    acc[mb][nt][2] = acc[mb][nt][3] = 0.0f;
                }
            }
        }
    }
}

// ---------------------------------------------------------------------------
extern "C" void kernel_launch(void* const* d_in, const int* in_sizes, int n_in,
                              void* d_out, int out_size) {
    const float* x   = (const float*)d_in[0];
    const float* W   = (const float*)d_in[1];
    const float* b   = (const float*)d_in[2];
    const float* ps  = (const float*)d_in[3];
    const float* ent = (const float*)d_in[4];
    float* out = (float*)d_out;

    cudaFuncSetAttribute(qnl_kernel,
                         cudaFuncAttributeMaxDynamicSharedMemorySize, SMEM_BYTES);

    qnl_kernel<<<NCTAS, NTHREADS, SMEM_BYTES>>>(x, W, b, ps, ent, out);
}

// round 15
// speedup vs baseline: 1.0233x; 1.0233x over previous
#include <cuda_runtime.h>
#include <cstdint>

// ============================================================================
// QuantumNeuralLayer: out = x @ W.T + (b + 0.1*q); q batch-independent.
// 262144x256x64 fp32 GEMM via mma.sync fp16.
// R15: per-warp MLP experiment. R6-R14 data shows per-warp stage period is
// CONSTANT (~1.2us / 4KB stage) across dtype/warps/CTAs => BW is pinned by
// bytes-in-flight per warp (3 stages x 4KB), not by any service ceiling.
// Fix: 5-slot ring + wait_group 3 -> 4 stages (16KB) in flight per warp
// (+33%). fp16 Wf (32KB) frees the SMEM for the 5th slot: 5x36+32 = 212KB.
// Everything else = R9 (tied-best): 8 warps x 32 rows, KCHUNK=32, per-warp
// barrier-free pipelines, single launch.
// ============================================================================

#define INV_SQRT2 0.70710678118654752440f

static constexpr int B_TOTAL = 262144;
static constexpr int KDIM    = 256;
static constexpr int ODIM    = 64;
static constexpr int TILE_M  = 256;                 // 8 warps x 32 rows
static constexpr int NTILES  = B_TOTAL / TILE_M;    // 1024
static constexpr int NTHREADS = 256;

static constexpr int KCHUNK   = 32;                 // floats per stage (2 k16)
static constexpr int SPT      = KDIM / KCHUNK;      // 8 stages per tile
static constexpr int NSLOTS   = 5;                  // ring depth
static constexpr int APITCH   = 40;                 // conflict-free for LDS.64
static constexpr int ASTAGE_F = TILE_M * APITCH;    // 10240 floats = 40 KB
static constexpr int WF_F     = NSLOTS * ASTAGE_F;  // 51200 (floats offset)
static constexpr int SMEM_F   = WF_F + 8192;        // Wf = 32 KB as fp16x2
static constexpr int SMEM_BYTES = SMEM_F * 4;       // 237568... check: 59392*4

// 5*10240 + 8192 = 59392 floats = 237568 B > 227KB limit! Shrink APITCH:
// use APITCH=36 with LDS.64: offsets r*36 + 2c (float2 units r*18+c):
// per phase lanes hit banks (r*36*4/8 + c) mod ... keep APITCH=36 and do
// LDS.32-based fragment loads (R6 style) to stay conflict-free.
// 5*9216 + 8192 = 54272 floats = 217088 B <= 232448 OK.
static constexpr int APITCH2   = 36;
static constexpr int ASTAGE2_F = TILE_M * APITCH2;   // 9216 floats = 36 KB
static constexpr int WF2_F     = NSLOTS * ASTAGE2_F; // 46080
static constexpr int SMEM2_F   = WF2_F + 8192;       // 54272
static constexpr int SMEM2_BYTES = SMEM2_F * 4;      // 217088 B

// Bias-prep scratch overlays ring slot 4 (first written at j=0, post-barrier).
static constexpr int HA_F = 4 * ASTAGE2_F;
static constexpr int HC_F = HA_F + 64;

__device__ float g_bias[64];   // b + 0.1*quantum; all CTAs write same values

// ---------------------------------------------------------------------------
__device__ __forceinline__ uint32_t smem_u32(const void* p) {
    uint32_t a;
    asm("{ .reg .u64 t; cvta.to.shared.u64 t, %1; cvt.u32.u64 %0, t; }" : "=r"(a) : "l"(p));
    return a;
}
__device__ __forceinline__ void cp_async16(uint32_t s, const void* g) {
    asm volatile("cp.async.cg.shared.global [%0], [%1], 16;" :: "r"(s), "l"(g));
}
#define CP_COMMIT() asm volatile("cp.async.commit_group;" ::: "memory")
#define CP_WAIT_3() asm volatile("cp.async.wait_group 3;" ::: "memory")

__device__ __forceinline__ uint32_t f2h2(float lo, float hi) {
    uint32_t r;
    asm("cvt.rn.f16x2.f32 %0, %1, %2;" : "=r"(r) : "f"(hi), "f"(lo));
    return r;
}

__device__ __forceinline__ void mma_f16(float c[4], uint32_t a0, uint32_t a1,
                                        uint32_t a2, uint32_t a3,
                                        uint32_t b0, uint32_t b1) {
    asm volatile(
        "mma.sync.aligned.m16n8k16.row.col.f32.f16.f16.f32 "
        "{%0,%1,%2,%3}, {%4,%5,%6,%7}, {%8,%9}, {%0,%1,%2,%3};"
        : "+f"(c[0]), "+f"(c[1]), "+f"(c[2]), "+f"(c[3])
        : "r"(a0), "r"(a1), "r"(a2), "r"(a3), "r"(b0), "r"(b1));
}

__device__ __forceinline__ int inc5(int s) { return s == NSLOTS - 1 ? 0 : s + 1; }

// ---------------------------------------------------------------------------
__global__ void __launch_bounds__(NTHREADS, 1)
qnl_kernel(const float* __restrict__ x, const float* __restrict__ W,
           const float* __restrict__ bvec, const float* __restrict__ phase,
           const float* __restrict__ ent, float* __restrict__ out) {
    extern __shared__ float smemf[];
    const uint32_t sb = smem_u32(smemf);
    const int tid  = threadIdx.x;
    const int wid  = tid >> 5;
    const int lane = tid & 31;
    const int grid = gridDim.x;
    const int bid  = blockIdx.x;

    // Warp owns rows [wid*32, wid*32+32); m-frags at arow/+8 (mb0), +16/+24 (mb1).
    const int wrow = wid * 32;
    const int arow = wrow + (lane >> 2);

    const int ntile_local = (NTILES - bid + grid - 1) / grid;
    const int H = SPT * ntile_local;   // >= 48 always (>= 6 tiles per CTA)

    // Per-warp stage load: this warp's 32 rows of k32-chunk (jq&7) of tile
    // (jq>>3), into given ring slot. 8 cp.async per lane.
    auto load_stage = [&](int jq, int slot) {
        const int tile = bid + (jq >> 3) * grid;
        const float* src = x + (size_t)tile * TILE_M * KDIM + (jq & 7) * KCHUNK;
        const uint32_t abase = sb + (uint32_t)(slot * ASTAGE2_F + wrow * APITCH2) * 4;
#pragma unroll
        for (int i = 0; i < 8; i++) {
            int c  = lane + 32 * i;        // 0..255
            int r  = c >> 3;               // local row 0..31
            int kc = c & 7;                // 16B chunk within 32-float chunk
            cp_async16(abase + (uint32_t)(r * APITCH2 + kc * 4) * 4,
                       src + (size_t)(wrow + r) * KDIM + kc * 4);
        }
        CP_COMMIT();
    };

    // Prologue: 4 stages in flight (slots 0..3); prep under the latency.
    load_stage(0, 0);
    load_stage(1, 1);
    load_stage(2, 2);
    load_stage(3, 3);

    // --- W fragments, fp16x2: layout [s(16)][nt(8)][lane(32)] uint2{b0,b1} ---
    for (int e = tid; e < 4096; e += NTHREADS) {
        int le = e & 31;
        int nt = (e >> 5) & 7;
        int s  = e >> 8;
        int n = nt * 8 + (le >> 2);
        int k = s * 16 + 2 * (le & 3);
        const float* wr = W + n * KDIM + k;
        uint2 wv;
        wv.x = f2h2(wr[0], wr[1]);
        wv.y = f2h2(wr[8], wr[9]);
        ((uint2*)(smemf + WF2_F))[e] = wv;
    }

    // --- bias_eff = b + 0.1*quantum (scratch overlays ring slot 4) ---
    {
        float a = 1.0f, c = 0.0f;
        for (int d = 0; d < 3; d++) {
            if (tid < 64) {
                float ph = phase[d * 64 + tid];
                smemf[HA_F + tid] = (a + c) * INV_SQRT2 * sinf(ph);
                smemf[HC_F + tid] = (a - c) * INV_SQRT2 * cosf(ph);
            }
            __syncthreads();
            if (tid < 64) {
                float sa = 0.0f, sc = 0.0f;
#pragma unroll
                for (int i = 0; i < 64; i++) {
                    float e = ent[i * 64 + tid];
                    sa += smemf[HA_F + i] * e;
                    sc += smemf[HC_F + i] * e;
                }
                a = sa; c = sc;
            }
            __syncthreads();
        }
        if (tid < 64) g_bias[tid] = bvec[tid] + 0.1f * (a * a + c * c);
    }
    __syncthreads();   // Wf visible, scratch retired; only CTA-wide barrier

    float acc[2][8][4];
#pragma unroll
    for (int mb = 0; mb < 2; mb++)
#pragma unroll
        for (int nt = 0; nt < 8; nt++)
#pragma unroll
            for (int q = 0; q < 4; q++) acc[mb][nt][q] = 0.0f;

    const uint2* Wb = (const uint2*)(smemf + WF2_F);

    int slot_l = 4;   // next load slot (stage 4 goes here at j=0)
    int slot_c = 0;   // compute slot for stage j

    for (int j = 0; j < H; j++) {
        CP_WAIT_3();       // stage j resident; j+1..j+3 may be in flight
        __syncwarp();      // whole warp's chunks resident

        if (j + 4 < H) load_stage(j + 4, slot_l);
        else CP_COMMIT();  // uniform group accounting
        slot_l = inc5(slot_l);

        // A fragments: LDS.32 of fp32, cvt fp16x2 (conflict-free pitch 36).
        const float* Ab = smemf + slot_c * ASTAGE2_F + arow * APITCH2 + 2 * (lane & 3);
        slot_c = inc5(slot_c);
        const int sbase = (j & 7) * 2;

#pragma unroll
        for (int sl = 0; sl < 2; sl++) {
            const int ko = sl * 16;
            uint32_t a0 = f2h2(Ab[ko],                    Ab[ko + 1]);
            uint32_t a1 = f2h2(Ab[ko + 8 * APITCH2],      Ab[ko + 1 + 8 * APITCH2]);
            uint32_t a2 = f2h2(Ab[ko + 8],                Ab[ko + 9]);
            uint32_t a3 = f2h2(Ab[ko + 8 + 8 * APITCH2],  Ab[ko + 9 + 8 * APITCH2]);
            uint32_t c0 = f2h2(Ab[ko + 16 * APITCH2],     Ab[ko + 1 + 16 * APITCH2]);
            uint32_t c1 = f2h2(Ab[ko + 24 * APITCH2],     Ab[ko + 1 + 24 * APITCH2]);
            uint32_t c2 = f2h2(Ab[ko + 8 + 16 * APITCH2], Ab[ko + 9 + 16 * APITCH2]);
            uint32_t c3 = f2h2(Ab[ko + 8 + 24 * APITCH2], Ab[ko + 9 + 24 * APITCH2]);
            const int s = sbase + sl;
#pragma unroll
            for (int nt = 0; nt < 8; nt++) {
                uint2 wv = Wb[(s * 8 + nt) * 32 + lane];
                mma_f16(acc[0][nt], a0, a1, a2, a3, wv.x, wv.y);
                mma_f16(acc[1][nt], c0, c1, c2, c3, wv.x, wv.y);
            }
        }

        if ((j & 7) == 7) {
            // Tile complete: per-warp epilogue; bias via global (L1/L2 hit).
            const int tile = bid + (j >> 3) * grid;
            const int row0 = tile * TILE_M + arow;
            float* o0 = out + (size_t)row0 * ODIM + 2 * (lane & 3);
#pragma unroll
            for (int mb = 0; mb < 2; mb++) {
                float* om = o0 + (size_t)(mb * 16) * ODIM;
#pragma unroll
                for (int nt = 0; nt < 8; nt++) {
                    const int cb = nt * 8;
                    float bx = g_bias[cb + 2 * (lane & 3)];
                    float by = g_bias[cb + 2 * (lane & 3) + 1];
                    float2 v0 = {acc[mb][nt][0] + bx, acc[mb][nt][1] + by};
                    float2 v1 = {acc[mb][nt][2] + bx, acc[mb][nt][3] + by};
                    *(float2*)(om + cb)            = v0;
                    *(float2*)(om + cb + 8 * ODIM) = v1;
                    acc[mb][nt][0] = acc[mb][nt][1] = 0.0f;
                    acc[mb][nt][2] = acc[mb][nt][3] = 0.0f;
                }
            }
        }
    }
}

// ---------------------------------------------------------------------------
extern "C" void kernel_launch(void* const* d_in, const int* in_sizes, int n_in,
                              void* d_out, int out_size) {
    const float* x   = (const float*)d_in[0];
    const float* W   = (const float*)d_in[1];
    const float* b   = (const float*)d_in[2];
    const float* ps  = (const float*)d_in[3];
    const float* ent = (const float*)d_in[4];
    float* out = (float*)d_out;

    cudaFuncSetAttribute(qnl_kernel,
                         cudaFuncAttributeMaxDynamicSharedMemorySize, SMEM2_BYTES);

    int sm = 148;
    cudaDeviceGetAttribute(&sm, cudaDevAttrMultiProcessorCount, 0);
    int grid = sm < NTILES ? sm : NTILES;

    qnl_kernel<<<grid, NTHREADS, SMEM2_BYTES>>>(x, W, b, ps, ent, out);
}

// round 16
// speedup vs baseline: 1.1552x; 1.1289x over previous
#include <cuda_runtime.h>
#include <cstdint>

// ============================================================================
// QuantumNeuralLayer: out = x @ W.T + (b + 0.1*q); q batch-independent.
// 262144x256x64 fp32 GEMM via mma.sync tf32 — R6 config verbatim (measured
// best: 66.0us kernel / 69.7us total) with ONE change:
// R16: issue stage j+3's cp.asyncs BEFORE cp.async.wait_group (wait 3, not
// 2). During every wait the warp now has 3 stages (12KB) outstanding instead
// of 2 (8KB) — demand stays high exactly while the warp sleeps. Slot reuse
// is safe: slot (j+3)&3 == (j-1)&3, whose compute finished in program order.
// ============================================================================

#define INV_SQRT2 0.70710678118654752440f

static constexpr int B_TOTAL = 262144;
static constexpr int KDIM    = 256;
static constexpr int ODIM    = 64;
static constexpr int TILE_M  = 256;                 // 8 warps x 32 rows
static constexpr int NTILES  = B_TOTAL / TILE_M;    // 1024
static constexpr int NTHREADS = 256;

static constexpr int KCHUNK   = 32;                 // floats per stage
static constexpr int SPT      = KDIM / KCHUNK;      // 8 stages per tile
static constexpr int APITCH   = 36;                 // floats; frag-conflict-free
static constexpr int ASTAGE_F = TILE_M * APITCH;    // 9216 floats = 36 KB
static constexpr int WF_F     = 4 * ASTAGE_F;       // 36864
static constexpr int BIAS_F   = WF_F + 16384;       // 53248
static constexpr int HA_F     = BIAS_F + 64;
static constexpr int HC_F     = HA_F + 64;
static constexpr int SMEM_F   = HC_F + 64;
static constexpr int SMEM_BYTES = SMEM_F * 4;       // 213760 B

// ---------------------------------------------------------------------------
__device__ __forceinline__ uint32_t smem_u32(const void* p) {
    uint32_t a;
    asm("{ .reg .u64 t; cvta.to.shared.u64 t, %1; cvt.u32.u64 %0, t; }" : "=r"(a) : "l"(p));
    return a;
}
__device__ __forceinline__ void cp_async16(uint32_t s, const void* g) {
    asm volatile("cp.async.cg.shared.global [%0], [%1], 16;" :: "r"(s), "l"(g));
}
#define CP_COMMIT() asm volatile("cp.async.commit_group;" ::: "memory")
#define CP_WAIT_3() asm volatile("cp.async.wait_group 3;" ::: "memory")

__device__ __forceinline__ uint32_t f2tf32(float f) {
    uint32_t u;
    asm("cvt.rna.tf32.f32 %0, %1;" : "=r"(u) : "f"(f));
    return u;
}

__device__ __forceinline__ void mma_tf32(float c[4], uint32_t a0, uint32_t a1,
                                         uint32_t a2, uint32_t a3,
                                         uint32_t b0, uint32_t b1) {
    asm volatile(
        "mma.sync.aligned.m16n8k8.row.col.f32.tf32.tf32.f32 "
        "{%0,%1,%2,%3}, {%4,%5,%6,%7}, {%8,%9}, {%0,%1,%2,%3};"
        : "+f"(c[0]), "+f"(c[1]), "+f"(c[2]), "+f"(c[3])
        : "r"(a0), "r"(a1), "r"(a2), "r"(a3), "r"(b0), "r"(b1));
}

// ---------------------------------------------------------------------------
__global__ void __launch_bounds__(NTHREADS, 1)
qnl_kernel(const float* __restrict__ x, const float* __restrict__ W,
           const float* __restrict__ bvec, const float* __restrict__ phase,
           const float* __restrict__ ent, float* __restrict__ out) {
    extern __shared__ float smemf[];
    const uint32_t sb = smem_u32(smemf);
    const int tid  = threadIdx.x;
    const int wid  = tid >> 5;
    const int lane = tid & 31;
    const int grid = gridDim.x;
    const int bid  = blockIdx.x;

    // Warp owns rows [wid*32, wid*32+32); m-frags at +0 and +16.
    const int wrow = wid * 32;
    const int arow = wrow + (lane >> 2);

    const int ntile_local = (NTILES - bid + grid - 1) / grid;
    const int H = SPT * ntile_local;   // K-chunk stages per CTA

    // Per-warp stage load: this warp's 32 rows of k-chunk (jq&7) of tile
    // (jq>>3), into ring slot jq&3. 256 x 16B chunks -> 8 per lane.
    auto load_stage = [&](int jq) {
        const int tile = bid + (jq >> 3) * grid;
        const float* src = x + (size_t)tile * TILE_M * KDIM + (jq & 7) * KCHUNK;
        const uint32_t abase = sb + (uint32_t)((jq & 3) * ASTAGE_F + wrow * APITCH) * 4;
#pragma unroll
        for (int i = 0; i < 8; i++) {
            int c  = lane + 32 * i;        // 0..255
            int r  = c >> 3;               // local row 0..31
            int kc = c & 7;                // 16B chunk within 32-float chunk
            cp_async16(abase + (uint32_t)(r * APITCH + kc * 4) * 4,
                       src + (size_t)(wrow + r) * KDIM + kc * 4);
        }
        CP_COMMIT();
    };

    // Prologue: fill 3 stages (per warp), prep Wf + bias under the latency.
    load_stage(0);
    load_stage(1);
    load_stage(2);

    // --- W fragments: tf32-rounded, layout [s(32)][nt(8)][lane(32)] float2 ---
    for (int e = tid; e < 8192; e += NTHREADS) {
        int le = e & 31;
        int nt = (e >> 5) & 7;
        int s  = e >> 8;
        int n = nt * 8 + (le >> 2);
        int k = s * 8 + (le & 3);
        float2 wf;
        wf.x = __uint_as_float(f2tf32(W[n * KDIM + k]));
        wf.y = __uint_as_float(f2tf32(W[n * KDIM + k + 4]));
        *(float2*)(smemf + WF_F + 2 * e) = wf;
    }

    // --- bias_eff = b + 0.1*quantum (batch-independent) ---
    {
        float a = 1.0f, c = 0.0f;
        for (int d = 0; d < 3; d++) {
            if (tid < 64) {
                float ph = phase[d * 64 + tid];
                smemf[HA_F + tid] = (a + c) * INV_SQRT2 * sinf(ph);
                smemf[HC_F + tid] = (a - c) * INV_SQRT2 * cosf(ph);
            }
            __syncthreads();
            if (tid < 64) {
                float sa = 0.0f, sc = 0.0f;
#pragma unroll
                for (int i = 0; i < 64; i++) {
                    float e = ent[i * 64 + tid];
                    sa += smemf[HA_F + i] * e;
                    sc += smemf[HC_F + i] * e;
                }
                a = sa; c = sc;
            }
            __syncthreads();
        }
        if (tid < 64) smemf[BIAS_F + tid] = bvec[tid] + 0.1f * (a * a + c * c);
    }
    __syncthreads();   // Wf + bias visible; ONLY CTA-wide barrier in kernel

    float2 bias[8];
#pragma unroll
    for (int nt = 0; nt < 8; nt++) {
        int col = nt * 8 + 2 * (lane & 3);
        bias[nt].x = smemf[BIAS_F + col];
        bias[nt].y = smemf[BIAS_F + col + 1];
    }

    float acc[2][8][4];
#pragma unroll
    for (int mb = 0; mb < 2; mb++)
#pragma unroll
        for (int nt = 0; nt < 8; nt++)
#pragma unroll
            for (int q = 0; q < 4; q++) acc[mb][nt][q] = 0.0f;

    const float2* Wb = (const float2*)(smemf + WF_F);

    for (int j = 0; j < H; j++) {
        // Issue stage j+3 BEFORE waiting: slot (j+3)&3 == (j-1)&3, whose
        // compute completed in program order last iteration. Keeps 3 stages
        // outstanding during the wait instead of 2.
        if (j + 3 < H) load_stage(j + 3);
        else CP_COMMIT();  // uniform group accounting in the tail

        CP_WAIT_3();       // stage j resident (j+1..j+3 may remain in flight)
        __syncwarp();      // whole warp's chunks resident

        const float* Ab = smemf + (j & 3) * ASTAGE_F + arow * APITCH + (lane & 3);
        const int sbase = (j & 7) * 4;

#pragma unroll
        for (int sl = 0; sl < 4; sl++) {
            const int ko = sl * 8;
            uint32_t a0 = f2tf32(Ab[ko]);
            uint32_t a1 = f2tf32(Ab[ko + 8 * APITCH]);
            uint32_t a2 = f2tf32(Ab[ko + 4]);
            uint32_t a3 = f2tf32(Ab[ko + 4 + 8 * APITCH]);
            uint32_t b0 = f2tf32(Ab[ko + 16 * APITCH]);
            uint32_t b1 = f2tf32(Ab[ko + 24 * APITCH]);
            uint32_t b2 = f2tf32(Ab[ko + 4 + 16 * APITCH]);
            uint32_t b3 = f2tf32(Ab[ko + 4 + 24 * APITCH]);
            const int s = sbase + sl;
#pragma unroll
            for (int nt = 0; nt < 8; nt++) {
                float2 wf = Wb[(s * 8 + nt) * 32 + lane];
                uint32_t w0 = __float_as_uint(wf.x);
                uint32_t w1 = __float_as_uint(wf.y);
                mma_tf32(acc[0][nt], a0, a1, a2, a3, w0, w1);
                mma_tf32(acc[1][nt], b0, b1, b2, b3, w0, w1);
            }
        }

        if ((j & 7) == 7) {
            // Tile complete: per-warp epilogue, no barriers.
            const int tile = bid + (j >> 3) * grid;
            const int row0 = tile * TILE_M + arow;
            float* o0 = out + (size_t)row0 * ODIM + 2 * (lane & 3);
#pragma unroll
            for (int mb = 0; mb < 2; mb++) {
                float* om = o0 + (size_t)(mb * 16) * ODIM;
#pragma unroll
                for (int nt = 0; nt < 8; nt++) {
                    const int cb = nt * 8;
                    float2 v0 = {acc[mb][nt][0] + bias[nt].x,
                                 acc[mb][nt][1] + bias[nt].y};
                    float2 v1 = {acc[mb][nt][2] + bias[nt].x,
                                 acc[mb][nt][3] + bias[nt].y};
                    *(float2*)(om + cb)            = v0;
                    *(float2*)(om + cb + 8 * ODIM) = v1;
                    acc[mb][nt][0] = acc[mb][nt][1] = 0.0f;
                    acc[mb][nt][2] = acc[mb][nt][3] = 0.0f;
                }
            }
        }
    }
}

// ---------------------------------------------------------------------------
extern "C" void kernel_launch(void* const* d_in, const int* in_sizes, int n_in,
                              void* d_out, int out_size) {
    const float* x   = (const float*)d_in[0];
    const float* W   = (const float*)d_in[1];
    const float* b   = (const float*)d_in[2];
    const float* ps  = (const float*)d_in[3];
    const float* ent = (const float*)d_in[4];
    float* out = (float*)d_out;

    cudaFuncSetAttribute(qnl_kernel,
                         cudaFuncAttributeMaxDynamicSharedMemorySize, SMEM_BYTES);

    int sm = 148;
    cudaDeviceGetAttribute(&sm, cudaDevAttrMultiProcessorCount, 0);
    int grid = sm < NTILES ? sm : NTILES;

    qnl_kernel<<<grid, NTHREADS, SMEM_BYTES>>>(x, W, b, ps, ent, out);
}